// round 6
// baseline (speedup 1.0000x reference)
#include <cuda_runtime.h>
#include <cuda_bf16.h>
#include <cstdint>
#include <math.h>

// Problem constants
#define BB 4
#define TT 2048
#define CC 1024
#define HH 16
#define DD 64
#define C3 3072          // 3*C
#define MTOT 8192        // B*T

// Scratch (device globals — no allocation in kernel_launch)
__device__ __nv_bfloat16 g_xh[(size_t)MTOT * CC];
__device__ __nv_bfloat16 g_xl[(size_t)MTOT * CC];
__device__ __nv_bfloat16 g_wqh[(size_t)C3 * CC];
__device__ __nv_bfloat16 g_wql[(size_t)C3 * CC];
__device__ __nv_bfloat16 g_woh[(size_t)CC * CC];
__device__ __nv_bfloat16 g_wol[(size_t)CC * CC];
__device__ __nv_bfloat16 g_qkvh[(size_t)MTOT * C3];
__device__ __nv_bfloat16 g_qkvl[(size_t)MTOT * C3];
__device__ __nv_bfloat16 g_ath[(size_t)MTOT * CC];
__device__ __nv_bfloat16 g_atl[(size_t)MTOT * CC];

// ---------------------------------------------------------------------------
// Helpers
// ---------------------------------------------------------------------------
__device__ __forceinline__ unsigned sptr(const void* p) {
    return (unsigned)__cvta_generic_to_shared(p);
}

__device__ __forceinline__ void ldsm4(unsigned& r0, unsigned& r1,
                                      unsigned& r2, unsigned& r3, unsigned a) {
    asm volatile("ldmatrix.sync.aligned.m8n8.x4.shared.b16 {%0,%1,%2,%3}, [%4];"
                 : "=r"(r0), "=r"(r1), "=r"(r2), "=r"(r3) : "r"(a));
}

__device__ __forceinline__ void ldsm4t(unsigned& r0, unsigned& r1,
                                       unsigned& r2, unsigned& r3, unsigned a) {
    asm volatile("ldmatrix.sync.aligned.m8n8.x4.trans.shared.b16 {%0,%1,%2,%3}, [%4];"
                 : "=r"(r0), "=r"(r1), "=r"(r2), "=r"(r3) : "r"(a));
}

__device__ __forceinline__ void mma16816(float* c, const unsigned* a,
                                         unsigned b0, unsigned b1) {
    asm volatile(
        "mma.sync.aligned.m16n8k16.row.col.f32.bf16.bf16.f32 "
        "{%0,%1,%2,%3},{%4,%5,%6,%7},{%8,%9},{%0,%1,%2,%3};"
        : "+f"(c[0]), "+f"(c[1]), "+f"(c[2]), "+f"(c[3])
        : "r"(a[0]), "r"(a[1]), "r"(a[2]), "r"(a[3]), "r"(b0), "r"(b1));
}

// fp32 pair -> packed bf16 hi + packed bf16 lo
__device__ __forceinline__ void split2(float x, float y, unsigned& h, unsigned& l) {
    __nv_bfloat162 hh = __floats2bfloat162_rn(x, y);
    float hx = __bfloat162float(hh.x);
    float hy = __bfloat162float(hh.y);
    __nv_bfloat162 ll = __floats2bfloat162_rn(x - hx, y - hy);
    h = *(unsigned*)&hh;
    l = *(unsigned*)&ll;
}

// exact *0.125 on packed bf16x2 (exponent shift)
__device__ __forceinline__ unsigned scale8(unsigned v) {
    __nv_bfloat162 t = *(__nv_bfloat162*)&v;
    __nv_bfloat162 s = __floats2bfloat162_rn(0.125f, 0.125f);
    t = __hmul2(t, s);
    return *(unsigned*)&t;
}

// cp.async
__device__ __forceinline__ void cp16(unsigned saddr, const void* g) {
    asm volatile("cp.async.cg.shared.global [%0], [%1], 16;\n"
                 :: "r"(saddr), "l"(g));
}
template<int N> __device__ __forceinline__ void cp_wait() {
    asm volatile("cp.async.wait_group %0;\n" :: "n"(N) : "memory");
}
__device__ __forceinline__ void cp_commit() {
    asm volatile("cp.async.commit_group;\n" ::: "memory");
}

// ---------------------------------------------------------------------------
// fp32 -> (bf16 hi, bf16 lo) split. n multiple of 4.
// ---------------------------------------------------------------------------
__global__ __launch_bounds__(256) void split_bf16(
    const float* __restrict__ x,
    __nv_bfloat16* __restrict__ hi, __nv_bfloat16* __restrict__ lo, int n)
{
    int base = (blockIdx.x * blockDim.x + threadIdx.x) * 4;
    if (base >= n) return;
    float4 v = *(const float4*)(x + base);
    unsigned h01, l01, h23, l23;
    split2(v.x, v.y, h01, l01);
    split2(v.z, v.w, h23, l23);
    *(unsigned*)(hi + base)     = h01;
    *(unsigned*)(hi + base + 2) = h23;
    *(unsigned*)(lo + base)     = l01;
    *(unsigned*)(lo + base + 2) = l23;
}

// ---------------------------------------------------------------------------
// HMMA GEMM v2 (NT): C = A*W^T (+bias), bf16 split (hh + hl + lh).
// CTA tile 256x128, 8 warps in 4x2, warp tile 64x64, BK=32.
// cp.async double-buffered stages; ldmatrix fragment loads; PADK=40 rows
// (80B stride -> 8-row LDSM phases hit 8 distinct 16B banks: 5r mod 8 bijective).
// Dynamic smem: 2 stages x (A 256x40 hi/lo + W 128x40 hi/lo) = 2 x 60KB.
// ---------------------------------------------------------------------------
#define PADK 40
#define STAGE_BYTES 61440    // 20480(Ah) + 20480(Al) + 10240(Wh) + 10240(Wl)

__global__ __launch_bounds__(256, 1) void gemm_mma2(
    const __nv_bfloat16* __restrict__ Ah, const __nv_bfloat16* __restrict__ Al,
    const __nv_bfloat16* __restrict__ Wh, const __nv_bfloat16* __restrict__ Wl,
    float* __restrict__ Cf,
    __nv_bfloat16* __restrict__ Ch, __nv_bfloat16* __restrict__ Cl,
    const float* __restrict__ bias,
    int M, int N, int K)
{
    extern __shared__ __align__(16) __nv_bfloat16 sm[];

    const int tid  = threadIdx.x;
    const int lane = tid & 31;
    const int warp = tid >> 5;
    const int wm = (warp >> 1) * 64;    // warp row offset (4 rows of warps)
    const int wn = (warp & 1) * 64;     // warp col offset (2 cols of warps)
    const int brow = blockIdx.y * 256;
    const int bcol = blockIdx.x * 128;
    const int nch  = K >> 5;            // BK=32 slabs

    const int tt  = lane >> 3;
    const int lr8 = lane & 7;

    const unsigned smb = sptr(sm);

    float acc[4][8][4];
#pragma unroll
    for (int mt = 0; mt < 4; mt++)
#pragma unroll
        for (int nt = 0; nt < 8; nt++)
#pragma unroll
            for (int i = 0; i < 4; i++) acc[mt][nt][i] = 0.0f;

    // load K-slab c into stage s (12 cp16 per thread, one commit group)
    auto load_stage = [&](int c, int s) {
        const int k0 = c << 5;
        const unsigned sb = smb + (unsigned)s * STAGE_BYTES;
#pragma unroll
        for (int i = 0; i < 4; i++) {          // A: 256 rows x 32 cols
            int idx = i * 256 + tid;
            int row = idx >> 2;
            int cc  = (idx & 3) * 8;
            unsigned d = sb + (unsigned)(row * PADK + cc) * 2;
            size_t g = (size_t)(brow + row) * K + k0 + cc;
            cp16(d,         Ah + g);
            cp16(d + 20480, Al + g);
        }
#pragma unroll
        for (int i = 0; i < 2; i++) {          // W: 128 rows x 32 cols
            int idx = i * 256 + tid;
            int row = idx >> 2;
            int cc  = (idx & 3) * 8;
            unsigned d = sb + 40960u + (unsigned)(row * PADK + cc) * 2;
            size_t g = (size_t)(bcol + row) * K + k0 + cc;
            cp16(d,         Wh + g);
            cp16(d + 10240, Wl + g);
        }
        cp_commit();
    };

    load_stage(0, 0);
    load_stage(1, 1);

    for (int c = 0; c < nch; c++) {
        if (c + 1 < nch) cp_wait<1>();
        else             cp_wait<0>();
        __syncthreads();

        const unsigned sb = smb + (unsigned)(c & 1) * STAGE_BYTES;
        const unsigned sbW = sb + 40960u;

#pragma unroll
        for (int ks = 0; ks < 32; ks += 16) {
            unsigned bh[8][2], bl[8][2];
#pragma unroll
            for (int i = 0; i < 4; i++) {
                int nrow = wn + (2 * i + (tt >> 1)) * 8 + lr8;
                int ncol = ks + (tt & 1) * 8;
                unsigned a = sbW + (unsigned)(nrow * PADK + ncol) * 2;
                ldsm4(bh[2 * i][0], bh[2 * i][1], bh[2 * i + 1][0], bh[2 * i + 1][1], a);
                ldsm4(bl[2 * i][0], bl[2 * i][1], bl[2 * i + 1][0], bl[2 * i + 1][1], a + 10240);
            }
#pragma unroll
            for (int mt = 0; mt < 4; mt++) {
                int arow = wm + mt * 16 + (tt & 1) * 8 + lr8;
                int acol = ks + (tt >> 1) * 8;
                unsigned a = sb + (unsigned)(arow * PADK + acol) * 2;
                unsigned ah[4], al[4];
                ldsm4(ah[0], ah[1], ah[2], ah[3], a);
                ldsm4(al[0], al[1], al[2], al[3], a + 20480);
#pragma unroll
                for (int nt = 0; nt < 8; nt++) {
                    mma16816(acc[mt][nt], ah, bh[nt][0], bh[nt][1]);
                    mma16816(acc[mt][nt], ah, bl[nt][0], bl[nt][1]);
                    mma16816(acc[mt][nt], al, bh[nt][0], bh[nt][1]);
                }
            }
        }
        __syncthreads();
        if (c + 2 < nch) load_stage(c + 2, c & 1);
    }

    // Epilogue: c0:(r,2c) c1:(r,2c+1) c2:(r+8,2c) c3:(r+8,2c+1)
    const int r  = lane >> 2;
    const int cq = lane & 3;
#pragma unroll
    for (int mt = 0; mt < 4; mt++) {
#pragma unroll
        for (int nt = 0; nt < 8; nt++) {
            int row0 = brow + wm + mt * 16 + r;
            int col0 = bcol + wn + nt * 8 + cq * 2;
            float b0 = 0.f, b1 = 0.f;
            if (bias != nullptr) { b0 = bias[col0]; b1 = bias[col0 + 1]; }
            float v0 = acc[mt][nt][0] + b0, v1 = acc[mt][nt][1] + b1;
            float v2 = acc[mt][nt][2] + b0, v3 = acc[mt][nt][3] + b1;
            if (Cf != nullptr) {
                *(float2*)(Cf + (size_t)row0 * N + col0)       = make_float2(v0, v1);
                *(float2*)(Cf + (size_t)(row0 + 8) * N + col0) = make_float2(v2, v3);
            }
            if (Ch != nullptr) {
                unsigned h01, l01, h23, l23;
                split2(v0, v1, h01, l01);
                split2(v2, v3, h23, l23);
                *(unsigned*)(Ch + (size_t)row0 * N + col0)       = h01;
                *(unsigned*)(Cl + (size_t)row0 * N + col0)       = l01;
                *(unsigned*)(Ch + (size_t)(row0 + 8) * N + col0) = h23;
                *(unsigned*)(Cl + (size_t)(row0 + 8) * N + col0) = l23;
            }
        }
    }
}

// ---------------------------------------------------------------------------
// Tensor-core causal flash attention, split-bf16 (unchanged from R3 pass).
// Grid (16, 64). Br=128, Bc=64, 8 warps; warp w owns rows w*16..w*16+15.
// ---------------------------------------------------------------------------
#define SKP 72

__global__ __launch_bounds__(256) void flash_attn_mma(
    const __nv_bfloat16* __restrict__ qkvh,
    const __nv_bfloat16* __restrict__ qkvl,
    __nv_bfloat16* __restrict__ outh,
    __nv_bfloat16* __restrict__ outl)
{
    __shared__ __align__(16) __nv_bfloat16 sKh[64 * SKP];
    __shared__ __align__(16) __nv_bfloat16 sKl[64 * SKP];
    __shared__ __align__(16) __nv_bfloat16 sVh[64 * SKP];
    __shared__ __align__(16) __nv_bfloat16 sVl[64 * SKP];

    const int tid  = threadIdx.x;
    const int lane = tid & 31;
    const int w    = tid >> 5;
    const int qt   = (gridDim.x - 1) - blockIdx.x;
    const int bh   = blockIdx.y;
    const int b    = bh >> 4;
    const int h    = bh & 15;

    const int tt  = lane >> 3;
    const int lr8 = lane & 7;
    const int r   = lane >> 2;
    const int cq  = lane & 3;

    const int rowr  = qt * 128 + w * 16 + r;
    const int rowr8 = rowr + 8;

    unsigned qah[4][4], qal[4][4];
#pragma unroll
    for (int half = 0; half < 2; half++) {
        __syncthreads();
#pragma unroll
        for (int i = 0; i < 2; i++) {
            int idx = tid + i * 256;
            int row = idx >> 3;
            int c8  = (idx & 7) * 8;
            size_t g = (size_t)(b * TT + qt * 128 + half * 64 + row) * C3 + h * DD + c8;
            *(uint4*)(sKh + row * SKP + c8) = *(const uint4*)(qkvh + g);
            *(uint4*)(sKl + row * SKP + c8) = *(const uint4*)(qkvl + g);
        }
        __syncthreads();
        if ((w >> 2) == half) {
            int wq = (w & 3) * 16;
#pragma unroll
            for (int kc = 0; kc < 4; kc++) {
                int qrow = wq + (tt & 1) * 8 + lr8;
                int qcol = kc * 16 + (tt >> 1) * 8;
                ldsm4(qah[kc][0], qah[kc][1], qah[kc][2], qah[kc][3],
                      sptr(sKh + qrow * SKP + qcol));
                ldsm4(qal[kc][0], qal[kc][1], qal[kc][2], qal[kc][3],
                      sptr(sKl + qrow * SKP + qcol));
#pragma unroll
                for (int j = 0; j < 4; j++) {
                    qah[kc][j] = scale8(qah[kc][j]);
                    qal[kc][j] = scale8(qal[kc][j]);
                }
            }
        }
    }

    float o[8][4];
#pragma unroll
    for (int nt = 0; nt < 8; nt++)
#pragma unroll
        for (int j = 0; j < 4; j++) o[nt][j] = 0.0f;
    float m_r = -1e30f, m_r8 = -1e30f;
    float l_r = 0.0f,   l_r8 = 0.0f;

    const int nkt = 2 * qt + 2;

    uint4 pkh[2], pkl[2], pvh[2], pvl[2];
    {
        size_t base = (size_t)(b * TT) * C3 + h * DD;
#pragma unroll
        for (int i = 0; i < 2; i++) {
            int row = (tid >> 3) + i * 32;
            int c8  = (tid & 7) * 8;
            size_t gk = base + (size_t)row * C3 + CC + c8;
            size_t gv = base + (size_t)row * C3 + 2 * CC + c8;
            pkh[i] = *(const uint4*)(qkvh + gk);
            pkl[i] = *(const uint4*)(qkvl + gk);
            pvh[i] = *(const uint4*)(qkvh + gv);
            pvl[i] = *(const uint4*)(qkvl + gv);
        }
    }

    for (int kt = 0; kt < nkt; kt++) {
        __syncthreads();
#pragma unroll
        for (int i = 0; i < 2; i++) {
            int row = (tid >> 3) + i * 32;
            int c8  = (tid & 7) * 8;
            *(uint4*)(sKh + row * SKP + c8) = pkh[i];
            *(uint4*)(sKl + row * SKP + c8) = pkl[i];
            *(uint4*)(sVh + row * SKP + c8) = pvh[i];
            *(uint4*)(sVl + row * SKP + c8) = pvl[i];
        }
        __syncthreads();

        if (kt + 1 < nkt) {
            size_t base = (size_t)(b * TT + (kt + 1) * 64) * C3 + h * DD;
#pragma unroll
            for (int i = 0; i < 2; i++) {
                int row = (tid >> 3) + i * 32;
                int c8  = (tid & 7) * 8;
                size_t gk = base + (size_t)row * C3 + CC + c8;
                size_t gv = base + (size_t)row * C3 + 2 * CC + c8;
                pkh[i] = *(const uint4*)(qkvh + gk);
                pkl[i] = *(const uint4*)(qkvl + gk);
                pvh[i] = *(const uint4*)(qkvh + gv);
                pvl[i] = *(const uint4*)(qkvl + gv);
            }
        }

        if (kt * 64 <= qt * 128 + w * 16 + 15) {
            float s[8][4];
#pragma unroll
            for (int nt = 0; nt < 8; nt++)
#pragma unroll
                for (int j = 0; j < 4; j++) s[nt][j] = 0.0f;

#pragma unroll
            for (int kc = 0; kc < 4; kc++) {
                unsigned kbh[8][2], kbl[8][2];
#pragma unroll
                for (int i = 0; i < 4; i++) {
                    int nrow = (2 * i + (tt >> 1)) * 8 + lr8;
                    int ncol = kc * 16 + (tt & 1) * 8;
                    ldsm4(kbh[2 * i][0], kbh[2 * i][1], kbh[2 * i + 1][0], kbh[2 * i + 1][1],
                          sptr(sKh + nrow * SKP + ncol));
                    ldsm4(kbl[2 * i][0], kbl[2 * i][1], kbl[2 * i + 1][0], kbl[2 * i + 1][1],
                          sptr(sKl + nrow * SKP + ncol));
                }
#pragma unroll
                for (int nt = 0; nt < 8; nt++) {
                    mma16816(s[nt], qah[kc], kbh[nt][0], kbh[nt][1]);
                    mma16816(s[nt], qah[kc], kbl[nt][0], kbl[nt][1]);
                    mma16816(s[nt], qal[kc], kbh[nt][0], kbh[nt][1]);
                }
            }

            if (kt >= 2 * qt) {
                int colb = kt * 64 + cq * 2;
#pragma unroll
                for (int nt = 0; nt < 8; nt++) {
                    int c0 = colb + nt * 8;
                    if (c0 > rowr)      s[nt][0] = -1e30f;
                    if (c0 + 1 > rowr)  s[nt][1] = -1e30f;
                    if (c0 > rowr8)     s[nt][2] = -1e30f;
                    if (c0 + 1 > rowr8) s[nt][3] = -1e30f;
                }
            }

            float mr = -1e30f, mr8 = -1e30f;
#pragma unroll
            for (int nt = 0; nt < 8; nt++) {
                mr  = fmaxf(mr,  fmaxf(s[nt][0], s[nt][1]));
                mr8 = fmaxf(mr8, fmaxf(s[nt][2], s[nt][3]));
            }
            mr  = fmaxf(mr,  __shfl_xor_sync(0xffffffffu, mr, 1));
            mr  = fmaxf(mr,  __shfl_xor_sync(0xffffffffu, mr, 2));
            mr8 = fmaxf(mr8, __shfl_xor_sync(0xffffffffu, mr8, 1));
            mr8 = fmaxf(mr8, __shfl_xor_sync(0xffffffffu, mr8, 2));

            float mn  = fmaxf(m_r, mr);
            float mn8 = fmaxf(m_r8, mr8);
            float ar  = __expf(m_r - mn);
            float ar8 = __expf(m_r8 - mn8);
            m_r = mn; m_r8 = mn8;

            float lsr = 0.f, lsr8 = 0.f;
#pragma unroll
            for (int nt = 0; nt < 8; nt++) {
                float p0 = __expf(s[nt][0] - m_r);
                float p1 = __expf(s[nt][1] - m_r);
                float p2 = __expf(s[nt][2] - m_r8);
                float p3 = __expf(s[nt][3] - m_r8);
                lsr += p0 + p1; lsr8 += p2 + p3;
                s[nt][0] = p0; s[nt][1] = p1; s[nt][2] = p2; s[nt][3] = p3;
                o[nt][0] *= ar; o[nt][1] *= ar; o[nt][2] *= ar8; o[nt][3] *= ar8;
            }
            l_r  = l_r  * ar  + lsr;
            l_r8 = l_r8 * ar8 + lsr8;

#pragma unroll
            for (int kc = 0; kc < 4; kc++) {
                unsigned pah[4], pal[4];
                split2(s[2 * kc][0],     s[2 * kc][1],     pah[0], pal[0]);
                split2(s[2 * kc][2],     s[2 * kc][3],     pah[1], pal[1]);
                split2(s[2 * kc + 1][0], s[2 * kc + 1][1], pah[2], pal[2]);
                split2(s[2 * kc + 1][2], s[2 * kc + 1][3], pah[3], pal[3]);

                unsigned vbh[8][2], vbl[8][2];
#pragma unroll
                for (int i = 0; i < 4; i++) {
                    int vrow = kc * 16 + (tt & 1) * 8 + lr8;
                    int vcol = (2 * i + (tt >> 1)) * 8;
                    ldsm4t(vbh[2 * i][0], vbh[2 * i][1], vbh[2 * i + 1][0], vbh[2 * i + 1][1],
                           sptr(sVh + vrow * SKP + vcol));
                    ldsm4t(vbl[2 * i][0], vbl[2 * i][1], vbl[2 * i + 1][0], vbl[2 * i + 1][1],
                           sptr(sVl + vrow * SKP + vcol));
                }
#pragma unroll
                for (int nt = 0; nt < 8; nt++) {
                    mma16816(o[nt], pah, vbh[nt][0], vbh[nt][1]);
                    mma16816(o[nt], pah, vbl[nt][0], vbl[nt][1]);
                    mma16816(o[nt], pal, vbh[nt][0], vbh[nt][1]);
                }
            }
        }
    }

    l_r  += __shfl_xor_sync(0xffffffffu, l_r, 1);
    l_r  += __shfl_xor_sync(0xffffffffu, l_r, 2);
    l_r8 += __shfl_xor_sync(0xffffffffu, l_r8, 1);
    l_r8 += __shfl_xor_sync(0xffffffffu, l_r8, 2);
    float inv  = 1.0f / l_r;
    float inv8 = 1.0f / l_r8;

#pragma unroll
    for (int nt = 0; nt < 8; nt++) {
        unsigned h01, l01, h23, l23;
        split2(o[nt][0] * inv,  o[nt][1] * inv,  h01, l01);
        split2(o[nt][2] * inv8, o[nt][3] * inv8, h23, l23);
        size_t a0 = (size_t)(b * TT + rowr)  * CC + h * DD + nt * 8 + cq * 2;
        size_t a1 = (size_t)(b * TT + rowr8) * CC + h * DD + nt * 8 + cq * 2;
        *(unsigned*)(outh + a0) = h01;
        *(unsigned*)(outl + a0) = l01;
        *(unsigned*)(outh + a1) = h23;
        *(unsigned*)(outl + a1) = l23;
    }
}

// ---------------------------------------------------------------------------
extern "C" void kernel_launch(void* const* d_in, const int* in_sizes, int n_in,
                              void* d_out, int out_size)
{
    const float* x     = (const float*)d_in[0];
    const float* w_qkv = (const float*)d_in[1];
    const float* w_out = (const float*)d_in[2];
    const float* b_out = (const float*)d_in[3];
    float* out = (float*)d_out;

    __nv_bfloat16 *xh, *xl, *wqh, *wql, *woh, *wol, *qkvh, *qkvl, *ath, *atl;
    cudaGetSymbolAddress((void**)&xh,   g_xh);
    cudaGetSymbolAddress((void**)&xl,   g_xl);
    cudaGetSymbolAddress((void**)&wqh,  g_wqh);
    cudaGetSymbolAddress((void**)&wql,  g_wql);
    cudaGetSymbolAddress((void**)&woh,  g_woh);
    cudaGetSymbolAddress((void**)&wol,  g_wol);
    cudaGetSymbolAddress((void**)&qkvh, g_qkvh);
    cudaGetSymbolAddress((void**)&qkvl, g_qkvl);
    cudaGetSymbolAddress((void**)&ath,  g_ath);
    cudaGetSymbolAddress((void**)&atl,  g_atl);

    const int dsmem = 2 * STAGE_BYTES;   // 120KB double buffer
    cudaFuncSetAttribute(gemm_mma2, cudaFuncAttributeMaxDynamicSharedMemorySize, dsmem);

    // 0) split inputs
    {
        int n1 = MTOT * CC;
        split_bf16<<<(n1 / 4 + 255) / 256, 256>>>(x, xh, xl, n1);
        int n2 = C3 * CC;
        split_bf16<<<(n2 / 4 + 255) / 256, 256>>>(w_qkv, wqh, wql, n2);
        int n3 = CC * CC;
        split_bf16<<<(n3 / 4 + 255) / 256, 256>>>(w_out, woh, wol, n3);
    }

    // 1) QKV projection -> bf16 hi/lo
    {
        dim3 grid(C3 / 128, MTOT / 256);
        gemm_mma2<<<grid, 256, dsmem>>>(xh, xl, wqh, wql,
                                        nullptr, qkvh, qkvl, nullptr, MTOT, C3, CC);
    }

    // 2) causal flash attention -> bf16 hi/lo
    {
        dim3 grid(TT / 128, BB * HH);
        flash_attn_mma<<<grid, 256>>>(qkvh, qkvl, ath, atl);
    }

    // 3) out projection + bias -> fp32 output
    {
        dim3 grid(CC / 128, MTOT / 256);
        gemm_mma2<<<grid, 256, dsmem>>>(ath, atl, woh, wol,
                                        out, nullptr, nullptr, b_out, MTOT, CC, CC);
    }
}

// round 7
// speedup vs baseline: 1.4820x; 1.4820x over previous
#include <cuda_runtime.h>
#include <cuda_fp16.h>
#include <cstdint>
#include <math.h>

// Problem constants
#define BB 4
#define TT 2048
#define CC 1024
#define HH 16
#define DD 64
#define C3 3072          // 3*C
#define MTOT 8192        // B*T

// Scratch (device globals — no allocation in kernel_launch)
__device__ __half g_xh[(size_t)MTOT * CC];
__device__ __half g_xl[(size_t)MTOT * CC];
__device__ __half g_wqh[(size_t)C3 * CC];    // w_qkv rounded (single term)
__device__ __half g_woh[(size_t)CC * CC];    // w_out rounded (single term)
__device__ __half g_qkvh[(size_t)MTOT * C3];
__device__ __half g_qkvl[(size_t)MTOT * C3];
__device__ __half g_ath[(size_t)MTOT * CC];
__device__ __half g_atl[(size_t)MTOT * CC];

// ---------------------------------------------------------------------------
// Helpers
// ---------------------------------------------------------------------------
__device__ __forceinline__ unsigned sptr(const void* p) {
    return (unsigned)__cvta_generic_to_shared(p);
}

__device__ __forceinline__ void ldsm4(unsigned& r0, unsigned& r1,
                                      unsigned& r2, unsigned& r3, unsigned a) {
    asm volatile("ldmatrix.sync.aligned.m8n8.x4.shared.b16 {%0,%1,%2,%3}, [%4];"
                 : "=r"(r0), "=r"(r1), "=r"(r2), "=r"(r3) : "r"(a));
}

__device__ __forceinline__ void ldsm4t(unsigned& r0, unsigned& r1,
                                       unsigned& r2, unsigned& r3, unsigned a) {
    asm volatile("ldmatrix.sync.aligned.m8n8.x4.trans.shared.b16 {%0,%1,%2,%3}, [%4];"
                 : "=r"(r0), "=r"(r1), "=r"(r2), "=r"(r3) : "r"(a));
}

__device__ __forceinline__ void mma16816(float* c, const unsigned* a,
                                         unsigned b0, unsigned b1) {
    asm volatile(
        "mma.sync.aligned.m16n8k16.row.col.f32.f16.f16.f32 "
        "{%0,%1,%2,%3},{%4,%5,%6,%7},{%8,%9},{%0,%1,%2,%3};"
        : "+f"(c[0]), "+f"(c[1]), "+f"(c[2]), "+f"(c[3])
        : "r"(a[0]), "r"(a[1]), "r"(a[2]), "r"(a[3]), "r"(b0), "r"(b1));
}

// fp32 pair -> packed fp16 hi + packed fp16 lo (2-term exact split)
__device__ __forceinline__ void split2(float x, float y, unsigned& h, unsigned& l) {
    __half2 hh = __floats2half2_rn(x, y);
    float hx = __half2float(__low2half(hh));
    float hy = __half2float(__high2half(hh));
    __half2 ll = __floats2half2_rn(x - hx, y - hy);
    h = *(unsigned*)&hh;
    l = *(unsigned*)&ll;
}

// exact *0.125 on packed fp16x2 (exponent shift)
__device__ __forceinline__ unsigned scale8(unsigned v) {
    __half2 t = *(__half2*)&v;
    t = __hmul2(t, __floats2half2_rn(0.125f, 0.125f));
    return *(unsigned*)&t;
}

// ---------------------------------------------------------------------------
// fp32 -> fp16 hi/lo split (n multiple of 4), and fp32 -> fp16 round-only.
// ---------------------------------------------------------------------------
__global__ __launch_bounds__(256) void split_f16(
    const float* __restrict__ x,
    __half* __restrict__ hi, __half* __restrict__ lo, int n)
{
    int base = (blockIdx.x * blockDim.x + threadIdx.x) * 4;
    if (base >= n) return;
    float4 v = *(const float4*)(x + base);
    unsigned h01, l01, h23, l23;
    split2(v.x, v.y, h01, l01);
    split2(v.z, v.w, h23, l23);
    *(unsigned*)(hi + base)     = h01;
    *(unsigned*)(hi + base + 2) = h23;
    *(unsigned*)(lo + base)     = l01;
    *(unsigned*)(lo + base + 2) = l23;
}

__global__ __launch_bounds__(256) void round_f16(
    const float* __restrict__ x, __half* __restrict__ hi, int n)
{
    int base = (blockIdx.x * blockDim.x + threadIdx.x) * 4;
    if (base >= n) return;
    float4 v = *(const float4*)(x + base);
    __half2 h0 = __floats2half2_rn(v.x, v.y);
    __half2 h1 = __floats2half2_rn(v.z, v.w);
    *(unsigned*)(hi + base)     = *(unsigned*)&h0;
    *(unsigned*)(hi + base + 2) = *(unsigned*)&h1;
}

// ---------------------------------------------------------------------------
// HMMA GEMM (NT), fp16 2-term: C = (Ah+Al)*Wh^T (+bias).
// 128x128 CTA tile, BK=32, 8 warps 2x4, 64x32 warp tile, ldmatrix frags,
// register prefetch of next k-slab (R3 structure, Wl pipeline removed).
// ---------------------------------------------------------------------------
#define PADK 40

__global__ __launch_bounds__(256) void gemm_f16(
    const __half* __restrict__ Ah, const __half* __restrict__ Al,
    const __half* __restrict__ Wh,
    float* __restrict__ Cf,
    __half* __restrict__ Ch, __half* __restrict__ Cl,
    const float* __restrict__ bias,
    int M, int N, int K)
{
    __shared__ __align__(16) __half sAh[128 * PADK];
    __shared__ __align__(16) __half sAl[128 * PADK];
    __shared__ __align__(16) __half sWh[128 * PADK];

    const int tid  = threadIdx.x;
    const int lane = tid & 31;
    const int warp = tid >> 5;
    const int wm = (warp >> 2) * 64;
    const int wn = (warp & 3) * 32;
    const int brow = blockIdx.y * 128;
    const int bcol = blockIdx.x * 128;

    float acc[4][4][4];
#pragma unroll
    for (int mt = 0; mt < 4; mt++)
#pragma unroll
        for (int nt = 0; nt < 4; nt++)
#pragma unroll
            for (int i = 0; i < 4; i++) acc[mt][nt][i] = 0.0f;

    uint4 pah[2], pal[2], pwh[2];
#pragma unroll
    for (int i = 0; i < 2; i++) {
        int idx = tid + i * 256;
        int row = idx >> 2;
        int col = (idx & 3) * 8;
        pah[i] = *(const uint4*)(Ah + (size_t)(brow + row) * K + col);
        pal[i] = *(const uint4*)(Al + (size_t)(brow + row) * K + col);
        pwh[i] = *(const uint4*)(Wh + (size_t)(bcol + row) * K + col);
    }

    const int tt  = lane >> 3;
    const int lr8 = lane & 7;

    for (int k0 = 0; k0 < K; k0 += 32) {
        __syncthreads();
#pragma unroll
        for (int i = 0; i < 2; i++) {
            int idx = tid + i * 256;
            int row = idx >> 2;
            int col = (idx & 3) * 8;
            *(uint4*)(sAh + row * PADK + col) = pah[i];
            *(uint4*)(sAl + row * PADK + col) = pal[i];
            *(uint4*)(sWh + row * PADK + col) = pwh[i];
        }
        __syncthreads();

        if (k0 + 32 < K) {
#pragma unroll
            for (int i = 0; i < 2; i++) {
                int idx = tid + i * 256;
                int row = idx >> 2;
                int col = (idx & 3) * 8 + k0 + 32;
                pah[i] = *(const uint4*)(Ah + (size_t)(brow + row) * K + col);
                pal[i] = *(const uint4*)(Al + (size_t)(brow + row) * K + col);
                pwh[i] = *(const uint4*)(Wh + (size_t)(bcol + row) * K + col);
            }
        }

#pragma unroll
        for (int ks = 0; ks < 32; ks += 16) {
            unsigned bh[4][2];
#pragma unroll
            for (int i = 0; i < 2; i++) {
                int nrow = wn + (2 * i + (tt >> 1)) * 8 + lr8;
                int ncol = ks + (tt & 1) * 8;
                ldsm4(bh[2 * i][0], bh[2 * i][1], bh[2 * i + 1][0], bh[2 * i + 1][1],
                      sptr(sWh + nrow * PADK + ncol));
            }
#pragma unroll
            for (int mt = 0; mt < 4; mt++) {
                unsigned ah[4], al[4];
                int arow = wm + mt * 16 + (tt & 1) * 8 + lr8;
                int acol = ks + (tt >> 1) * 8;
                ldsm4(ah[0], ah[1], ah[2], ah[3], sptr(sAh + arow * PADK + acol));
                ldsm4(al[0], al[1], al[2], al[3], sptr(sAl + arow * PADK + acol));
#pragma unroll
                for (int nt = 0; nt < 4; nt++) {
                    mma16816(acc[mt][nt], ah, bh[nt][0], bh[nt][1]);
                    mma16816(acc[mt][nt], al, bh[nt][0], bh[nt][1]);
                }
            }
        }
    }

    const int r  = lane >> 2;
    const int cq = lane & 3;
#pragma unroll
    for (int mt = 0; mt < 4; mt++) {
#pragma unroll
        for (int nt = 0; nt < 4; nt++) {
            int row0 = brow + wm + mt * 16 + r;
            int col0 = bcol + wn + nt * 8 + cq * 2;
            float b0 = 0.f, b1 = 0.f;
            if (bias != nullptr) { b0 = bias[col0]; b1 = bias[col0 + 1]; }
            float v0 = acc[mt][nt][0] + b0, v1 = acc[mt][nt][1] + b1;
            float v2 = acc[mt][nt][2] + b0, v3 = acc[mt][nt][3] + b1;
            if (Cf != nullptr) {
                *(float2*)(Cf + (size_t)row0 * N + col0)       = make_float2(v0, v1);
                *(float2*)(Cf + (size_t)(row0 + 8) * N + col0) = make_float2(v2, v3);
            }
            if (Ch != nullptr) {
                unsigned h01, l01, h23, l23;
                split2(v0, v1, h01, l01);
                split2(v2, v3, h23, l23);
                *(unsigned*)(Ch + (size_t)row0 * N + col0)       = h01;
                *(unsigned*)(Cl + (size_t)row0 * N + col0)       = l01;
                *(unsigned*)(Ch + (size_t)(row0 + 8) * N + col0) = h23;
                *(unsigned*)(Cl + (size_t)(row0 + 8) * N + col0) = l23;
            }
        }
    }
}

// ---------------------------------------------------------------------------
// Causal flash attention, fp16 2-term: S = (Qh+Ql)Kh^T, O = (Ph+Pl)Vh.
// K and V use the hi term only (rounded-right). Grid (16, 64).
// Br=128, Bc=64, 8 warps; warp w owns rows w*16..w*16+15.
// ---------------------------------------------------------------------------
#define SKP 72   // smem row stride in fp16: 144B rows, LDSM conflict-free

__global__ __launch_bounds__(256) void flash_attn_f16(
    const __half* __restrict__ qkvh,
    const __half* __restrict__ qkvl,
    __half* __restrict__ outh,
    __half* __restrict__ outl)
{
    __shared__ __align__(16) __half sKh[64 * SKP];
    __shared__ __align__(16) __half sVh[64 * SKP];

    const int tid  = threadIdx.x;
    const int lane = tid & 31;
    const int w    = tid >> 5;
    const int qt   = (gridDim.x - 1) - blockIdx.x;   // heavy tiles first
    const int bh   = blockIdx.y;
    const int b    = bh >> 4;
    const int h    = bh & 15;

    const int tt  = lane >> 3;
    const int lr8 = lane & 7;
    const int r   = lane >> 2;
    const int cq  = lane & 3;

    const int rowr  = qt * 128 + w * 16 + r;
    const int rowr8 = rowr + 8;

    // ---- stage Q (two 64-row halves: hi in sKh, lo in sVh) ----
    unsigned qah[4][4], qal[4][4];
#pragma unroll
    for (int half = 0; half < 2; half++) {
        __syncthreads();
#pragma unroll
        for (int i = 0; i < 2; i++) {
            int idx = tid + i * 256;
            int row = idx >> 3;
            int c8  = (idx & 7) * 8;
            size_t g = (size_t)(b * TT + qt * 128 + half * 64 + row) * C3 + h * DD + c8;
            *(uint4*)(sKh + row * SKP + c8) = *(const uint4*)(qkvh + g);
            *(uint4*)(sVh + row * SKP + c8) = *(const uint4*)(qkvl + g);
        }
        __syncthreads();
        if ((w >> 2) == half) {
            int wq = (w & 3) * 16;
#pragma unroll
            for (int kc = 0; kc < 4; kc++) {
                int qrow = wq + (tt & 1) * 8 + lr8;
                int qcol = kc * 16 + (tt >> 1) * 8;
                ldsm4(qah[kc][0], qah[kc][1], qah[kc][2], qah[kc][3],
                      sptr(sKh + qrow * SKP + qcol));
                ldsm4(qal[kc][0], qal[kc][1], qal[kc][2], qal[kc][3],
                      sptr(sVh + qrow * SKP + qcol));
#pragma unroll
                for (int j = 0; j < 4; j++) {
                    qah[kc][j] = scale8(qah[kc][j]);   // fold 1/sqrt(D) (exact)
                    qal[kc][j] = scale8(qal[kc][j]);
                }
            }
        }
    }

    float o[8][4];
#pragma unroll
    for (int nt = 0; nt < 8; nt++)
#pragma unroll
        for (int j = 0; j < 4; j++) o[nt][j] = 0.0f;
    float m_r = -1e30f, m_r8 = -1e30f;
    float l_r = 0.0f,   l_r8 = 0.0f;

    const int nkt = 2 * qt + 2;

    // prefetch K/V tile 0 (hi terms only)
    uint4 pkh[2], pvh[2];
    {
        size_t base = (size_t)(b * TT) * C3 + h * DD;
#pragma unroll
        for (int i = 0; i < 2; i++) {
            int row = (tid >> 3) + i * 32;
            int c8  = (tid & 7) * 8;
            pkh[i] = *(const uint4*)(qkvh + base + (size_t)row * C3 + CC + c8);
            pvh[i] = *(const uint4*)(qkvh + base + (size_t)row * C3 + 2 * CC + c8);
        }
    }

    for (int kt = 0; kt < nkt; kt++) {
        __syncthreads();
#pragma unroll
        for (int i = 0; i < 2; i++) {
            int row = (tid >> 3) + i * 32;
            int c8  = (tid & 7) * 8;
            *(uint4*)(sKh + row * SKP + c8) = pkh[i];
            *(uint4*)(sVh + row * SKP + c8) = pvh[i];
        }
        __syncthreads();

        if (kt + 1 < nkt) {
            size_t base = (size_t)(b * TT + (kt + 1) * 64) * C3 + h * DD;
#pragma unroll
            for (int i = 0; i < 2; i++) {
                int row = (tid >> 3) + i * 32;
                int c8  = (tid & 7) * 8;
                pkh[i] = *(const uint4*)(qkvh + base + (size_t)row * C3 + CC + c8);
                pvh[i] = *(const uint4*)(qkvh + base + (size_t)row * C3 + 2 * CC + c8);
            }
        }

        if (kt * 64 <= qt * 128 + w * 16 + 15) {
            // ---- scores: S = (Qh+Ql)·Kh^T ----
            float s[8][4];
#pragma unroll
            for (int nt = 0; nt < 8; nt++)
#pragma unroll
                for (int j = 0; j < 4; j++) s[nt][j] = 0.0f;

#pragma unroll
            for (int kc = 0; kc < 4; kc++) {
                unsigned kbh[8][2];
#pragma unroll
                for (int i = 0; i < 4; i++) {
                    int nrow = (2 * i + (tt >> 1)) * 8 + lr8;
                    int ncol = kc * 16 + (tt & 1) * 8;
                    ldsm4(kbh[2 * i][0], kbh[2 * i][1], kbh[2 * i + 1][0], kbh[2 * i + 1][1],
                          sptr(sKh + nrow * SKP + ncol));
                }
#pragma unroll
                for (int nt = 0; nt < 8; nt++) {
                    mma16816(s[nt], qah[kc], kbh[nt][0], kbh[nt][1]);
                    mma16816(s[nt], qal[kc], kbh[nt][0], kbh[nt][1]);
                }
            }

            // ---- causal mask ----
            if (kt >= 2 * qt) {
                int colb = kt * 64 + cq * 2;
#pragma unroll
                for (int nt = 0; nt < 8; nt++) {
                    int c0 = colb + nt * 8;
                    if (c0 > rowr)      s[nt][0] = -1e30f;
                    if (c0 + 1 > rowr)  s[nt][1] = -1e30f;
                    if (c0 > rowr8)     s[nt][2] = -1e30f;
                    if (c0 + 1 > rowr8) s[nt][3] = -1e30f;
                }
            }

            // ---- online softmax ----
            float mr = -1e30f, mr8 = -1e30f;
#pragma unroll
            for (int nt = 0; nt < 8; nt++) {
                mr  = fmaxf(mr,  fmaxf(s[nt][0], s[nt][1]));
                mr8 = fmaxf(mr8, fmaxf(s[nt][2], s[nt][3]));
            }
            mr  = fmaxf(mr,  __shfl_xor_sync(0xffffffffu, mr, 1));
            mr  = fmaxf(mr,  __shfl_xor_sync(0xffffffffu, mr, 2));
            mr8 = fmaxf(mr8, __shfl_xor_sync(0xffffffffu, mr8, 1));
            mr8 = fmaxf(mr8, __shfl_xor_sync(0xffffffffu, mr8, 2));

            float mn  = fmaxf(m_r, mr);
            float mn8 = fmaxf(m_r8, mr8);
            float ar  = __expf(m_r - mn);
            float ar8 = __expf(m_r8 - mn8);
            m_r = mn; m_r8 = mn8;

            float lsr = 0.f, lsr8 = 0.f;
#pragma unroll
            for (int nt = 0; nt < 8; nt++) {
                float p0 = __expf(s[nt][0] - m_r);
                float p1 = __expf(s[nt][1] - m_r);
                float p2 = __expf(s[nt][2] - m_r8);
                float p3 = __expf(s[nt][3] - m_r8);
                lsr += p0 + p1; lsr8 += p2 + p3;
                s[nt][0] = p0; s[nt][1] = p1; s[nt][2] = p2; s[nt][3] = p3;
                o[nt][0] *= ar; o[nt][1] *= ar; o[nt][2] *= ar8; o[nt][3] *= ar8;
            }
            l_r  = l_r  * ar  + lsr;
            l_r8 = l_r8 * ar8 + lsr8;

            // ---- PV: O += (Ph+Pl)·Vh ----
#pragma unroll
            for (int kc = 0; kc < 4; kc++) {
                unsigned pah[4], pal[4];
                split2(s[2 * kc][0],     s[2 * kc][1],     pah[0], pal[0]);
                split2(s[2 * kc][2],     s[2 * kc][3],     pah[1], pal[1]);
                split2(s[2 * kc + 1][0], s[2 * kc + 1][1], pah[2], pal[2]);
                split2(s[2 * kc + 1][2], s[2 * kc + 1][3], pah[3], pal[3]);

                unsigned vbh[8][2];
#pragma unroll
                for (int i = 0; i < 4; i++) {
                    int vrow = kc * 16 + (tt & 1) * 8 + lr8;
                    int vcol = (2 * i + (tt >> 1)) * 8;
                    ldsm4t(vbh[2 * i][0], vbh[2 * i][1], vbh[2 * i + 1][0], vbh[2 * i + 1][1],
                           sptr(sVh + vrow * SKP + vcol));
                }
#pragma unroll
                for (int nt = 0; nt < 8; nt++) {
                    mma16816(o[nt], pah, vbh[nt][0], vbh[nt][1]);
                    mma16816(o[nt], pal, vbh[nt][0], vbh[nt][1]);
                }
            }
        }
    }

    l_r  += __shfl_xor_sync(0xffffffffu, l_r, 1);
    l_r  += __shfl_xor_sync(0xffffffffu, l_r, 2);
    l_r8 += __shfl_xor_sync(0xffffffffu, l_r8, 1);
    l_r8 += __shfl_xor_sync(0xffffffffu, l_r8, 2);
    float inv  = 1.0f / l_r;
    float inv8 = 1.0f / l_r8;

#pragma unroll
    for (int nt = 0; nt < 8; nt++) {
        unsigned h01, l01, h23, l23;
        split2(o[nt][0] * inv,  o[nt][1] * inv,  h01, l01);
        split2(o[nt][2] * inv8, o[nt][3] * inv8, h23, l23);
        size_t a0 = (size_t)(b * TT + rowr)  * CC + h * DD + nt * 8 + cq * 2;
        size_t a1 = (size_t)(b * TT + rowr8) * CC + h * DD + nt * 8 + cq * 2;
        *(unsigned*)(outh + a0) = h01;
        *(unsigned*)(outl + a0) = l01;
        *(unsigned*)(outh + a1) = h23;
        *(unsigned*)(outl + a1) = l23;
    }
}

// ---------------------------------------------------------------------------
extern "C" void kernel_launch(void* const* d_in, const int* in_sizes, int n_in,
                              void* d_out, int out_size)
{
    const float* x     = (const float*)d_in[0];
    const float* w_qkv = (const float*)d_in[1];
    const float* w_out = (const float*)d_in[2];
    const float* b_out = (const float*)d_in[3];
    float* out = (float*)d_out;

    __half *xh, *xl, *wqh, *woh, *qkvh, *qkvl, *ath, *atl;
    cudaGetSymbolAddress((void**)&xh,   g_xh);
    cudaGetSymbolAddress((void**)&xl,   g_xl);
    cudaGetSymbolAddress((void**)&wqh,  g_wqh);
    cudaGetSymbolAddress((void**)&woh,  g_woh);
    cudaGetSymbolAddress((void**)&qkvh, g_qkvh);
    cudaGetSymbolAddress((void**)&qkvl, g_qkvl);
    cudaGetSymbolAddress((void**)&ath,  g_ath);
    cudaGetSymbolAddress((void**)&atl,  g_atl);

    // 0) split activations (2-term), round weights (1-term)
    {
        int n1 = MTOT * CC;
        split_f16<<<(n1 / 4 + 255) / 256, 256>>>(x, xh, xl, n1);
        int n2 = C3 * CC;
        round_f16<<<(n2 / 4 + 255) / 256, 256>>>(w_qkv, wqh, n2);
        int n3 = CC * CC;
        round_f16<<<(n3 / 4 + 255) / 256, 256>>>(w_out, woh, n3);
    }

    // 1) QKV projection -> fp16 hi/lo
    {
        dim3 grid(C3 / 128, MTOT / 128);
        gemm_f16<<<grid, 256>>>(xh, xl, wqh,
                                nullptr, qkvh, qkvl, nullptr, MTOT, C3, CC);
    }

    // 2) causal flash attention -> fp16 hi/lo
    {
        dim3 grid(TT / 128, BB * HH);
        flash_attn_f16<<<grid, 256>>>(qkvh, qkvl, ath, atl);
    }

    // 3) out projection + bias -> fp32 output
    {
        dim3 grid(CC / 128, MTOT / 128);
        gemm_f16<<<grid, 256>>>(ath, atl, woh,
                                out, nullptr, nullptr, b_out, MTOT, CC, CC);
    }
}

// round 8
// speedup vs baseline: 2.3614x; 1.5934x over previous
#include <cuda_runtime.h>
#include <cuda_fp16.h>
#include <cstdint>
#include <math.h>

// Problem constants
#define BB 4
#define TT 2048
#define CC 1024
#define HH 16
#define DD 64
#define C3 3072          // 3*C
#define MTOT 8192        // B*T

// Scratch (device globals — no allocation in kernel_launch)
__device__ __half g_x16[(size_t)MTOT * CC];
__device__ __half g_wq16[(size_t)C3 * CC];
__device__ __half g_wo16[(size_t)CC * CC];
__device__ __half g_qkv16[(size_t)MTOT * C3];
__device__ __half g_at16[(size_t)MTOT * CC];

// ---------------------------------------------------------------------------
// Helpers
// ---------------------------------------------------------------------------
__device__ __forceinline__ unsigned sptr(const void* p) {
    return (unsigned)__cvta_generic_to_shared(p);
}

__device__ __forceinline__ void ldsm4(unsigned& r0, unsigned& r1,
                                      unsigned& r2, unsigned& r3, unsigned a) {
    asm volatile("ldmatrix.sync.aligned.m8n8.x4.shared.b16 {%0,%1,%2,%3}, [%4];"
                 : "=r"(r0), "=r"(r1), "=r"(r2), "=r"(r3) : "r"(a));
}

__device__ __forceinline__ void ldsm4t(unsigned& r0, unsigned& r1,
                                       unsigned& r2, unsigned& r3, unsigned a) {
    asm volatile("ldmatrix.sync.aligned.m8n8.x4.trans.shared.b16 {%0,%1,%2,%3}, [%4];"
                 : "=r"(r0), "=r"(r1), "=r"(r2), "=r"(r3) : "r"(a));
}

__device__ __forceinline__ void mma16816(float* c, const unsigned* a,
                                         unsigned b0, unsigned b1) {
    asm volatile(
        "mma.sync.aligned.m16n8k16.row.col.f32.f16.f16.f32 "
        "{%0,%1,%2,%3},{%4,%5,%6,%7},{%8,%9},{%0,%1,%2,%3};"
        : "+f"(c[0]), "+f"(c[1]), "+f"(c[2]), "+f"(c[3])
        : "r"(a[0]), "r"(a[1]), "r"(a[2]), "r"(a[3]), "r"(b0), "r"(b1));
}

__device__ __forceinline__ unsigned pack2(float x, float y) {
    __half2 h = __floats2half2_rn(x, y);
    return *(unsigned*)&h;
}

// exact *0.125 on packed fp16x2 (exponent shift)
__device__ __forceinline__ unsigned scale8(unsigned v) {
    __half2 t = *(__half2*)&v;
    t = __hmul2(t, __floats2half2_rn(0.125f, 0.125f));
    return *(unsigned*)&t;
}

// ---------------------------------------------------------------------------
// fp32 -> fp16 round. n multiple of 4.
// ---------------------------------------------------------------------------
__global__ __launch_bounds__(256) void round_f16(
    const float* __restrict__ x, __half* __restrict__ hi, int n)
{
    int base = (blockIdx.x * blockDim.x + threadIdx.x) * 4;
    if (base >= n) return;
    float4 v = *(const float4*)(x + base);
    *(unsigned*)(hi + base)     = pack2(v.x, v.y);
    *(unsigned*)(hi + base + 2) = pack2(v.z, v.w);
}

// ---------------------------------------------------------------------------
// HMMA GEMM (NT), fp16 1-term: C = A*W^T (+bias).
// 128x128 CTA tile, BK=32, 8 warps 2x4, 64x32 warp tile, ldmatrix frags,
// register prefetch of next k-slab. Output fp32 (Cf) or fp16 (Ch).
// ---------------------------------------------------------------------------
#define PADK 40

__global__ __launch_bounds__(256) void gemm_f16(
    const __half* __restrict__ A, const __half* __restrict__ W,
    float* __restrict__ Cf, __half* __restrict__ Ch,
    const float* __restrict__ bias,
    int M, int N, int K)
{
    __shared__ __align__(16) __half sA[128 * PADK];
    __shared__ __align__(16) __half sW[128 * PADK];

    const int tid  = threadIdx.x;
    const int lane = tid & 31;
    const int warp = tid >> 5;
    const int wm = (warp >> 2) * 64;
    const int wn = (warp & 3) * 32;
    const int brow = blockIdx.y * 128;
    const int bcol = blockIdx.x * 128;

    float acc[4][4][4];
#pragma unroll
    for (int mt = 0; mt < 4; mt++)
#pragma unroll
        for (int nt = 0; nt < 4; nt++)
#pragma unroll
            for (int i = 0; i < 4; i++) acc[mt][nt][i] = 0.0f;

    uint4 pa[2], pw[2];
#pragma unroll
    for (int i = 0; i < 2; i++) {
        int idx = tid + i * 256;
        int row = idx >> 2;
        int col = (idx & 3) * 8;
        pa[i] = *(const uint4*)(A + (size_t)(brow + row) * K + col);
        pw[i] = *(const uint4*)(W + (size_t)(bcol + row) * K + col);
    }

    const int tt  = lane >> 3;
    const int lr8 = lane & 7;

    for (int k0 = 0; k0 < K; k0 += 32) {
        __syncthreads();
#pragma unroll
        for (int i = 0; i < 2; i++) {
            int idx = tid + i * 256;
            int row = idx >> 2;
            int col = (idx & 3) * 8;
            *(uint4*)(sA + row * PADK + col) = pa[i];
            *(uint4*)(sW + row * PADK + col) = pw[i];
        }
        __syncthreads();

        if (k0 + 32 < K) {
#pragma unroll
            for (int i = 0; i < 2; i++) {
                int idx = tid + i * 256;
                int row = idx >> 2;
                int col = (idx & 3) * 8 + k0 + 32;
                pa[i] = *(const uint4*)(A + (size_t)(brow + row) * K + col);
                pw[i] = *(const uint4*)(W + (size_t)(bcol + row) * K + col);
            }
        }

#pragma unroll
        for (int ks = 0; ks < 32; ks += 16) {
            unsigned bw[4][2];
#pragma unroll
            for (int i = 0; i < 2; i++) {
                int nrow = wn + (2 * i + (tt >> 1)) * 8 + lr8;
                int ncol = ks + (tt & 1) * 8;
                ldsm4(bw[2 * i][0], bw[2 * i][1], bw[2 * i + 1][0], bw[2 * i + 1][1],
                      sptr(sW + nrow * PADK + ncol));
            }
#pragma unroll
            for (int mt = 0; mt < 4; mt++) {
                unsigned ah[4];
                int arow = wm + mt * 16 + (tt & 1) * 8 + lr8;
                int acol = ks + (tt >> 1) * 8;
                ldsm4(ah[0], ah[1], ah[2], ah[3], sptr(sA + arow * PADK + acol));
#pragma unroll
                for (int nt = 0; nt < 4; nt++)
                    mma16816(acc[mt][nt], ah, bw[nt][0], bw[nt][1]);
            }
        }
    }

    const int r  = lane >> 2;
    const int cq = lane & 3;
#pragma unroll
    for (int mt = 0; mt < 4; mt++) {
#pragma unroll
        for (int nt = 0; nt < 4; nt++) {
            int row0 = brow + wm + mt * 16 + r;
            int col0 = bcol + wn + nt * 8 + cq * 2;
            float b0 = 0.f, b1 = 0.f;
            if (bias != nullptr) { b0 = bias[col0]; b1 = bias[col0 + 1]; }
            float v0 = acc[mt][nt][0] + b0, v1 = acc[mt][nt][1] + b1;
            float v2 = acc[mt][nt][2] + b0, v3 = acc[mt][nt][3] + b1;
            if (Cf != nullptr) {
                *(float2*)(Cf + (size_t)row0 * N + col0)       = make_float2(v0, v1);
                *(float2*)(Cf + (size_t)(row0 + 8) * N + col0) = make_float2(v2, v3);
            }
            if (Ch != nullptr) {
                *(unsigned*)(Ch + (size_t)row0 * N + col0)       = pack2(v0, v1);
                *(unsigned*)(Ch + (size_t)(row0 + 8) * N + col0) = pack2(v2, v3);
            }
        }
    }
}

// ---------------------------------------------------------------------------
// Causal flash attention, fp16 1-term: S = Qh*Kh^T, O = Ph*Vh.
// Grid (16, 64). Br=128, Bc=64, 8 warps; warp w owns rows w*16..w*16+15.
// ---------------------------------------------------------------------------
#define SKP 72   // smem row stride in fp16: 144B rows, LDSM conflict-free

__global__ __launch_bounds__(256) void flash_attn_f16(
    const __half* __restrict__ qkv, __half* __restrict__ outp)
{
    __shared__ __align__(16) __half sK[64 * SKP];
    __shared__ __align__(16) __half sV[64 * SKP];

    const int tid  = threadIdx.x;
    const int lane = tid & 31;
    const int w    = tid >> 5;
    const int qt   = (gridDim.x - 1) - blockIdx.x;   // heavy tiles first
    const int bh   = blockIdx.y;
    const int b    = bh >> 4;
    const int h    = bh & 15;

    const int tt  = lane >> 3;
    const int lr8 = lane & 7;
    const int r   = lane >> 2;
    const int cq  = lane & 3;

    const int rowr  = qt * 128 + w * 16 + r;
    const int rowr8 = rowr + 8;

    // ---- stage Q (two 64-row halves through sK) and build Q fragments ----
    unsigned qa[4][4];
#pragma unroll
    for (int half = 0; half < 2; half++) {
        __syncthreads();
#pragma unroll
        for (int i = 0; i < 2; i++) {
            int idx = tid + i * 256;
            int row = idx >> 3;
            int c8  = (idx & 7) * 8;
            size_t g = (size_t)(b * TT + qt * 128 + half * 64 + row) * C3 + h * DD + c8;
            *(uint4*)(sK + row * SKP + c8) = *(const uint4*)(qkv + g);
        }
        __syncthreads();
        if ((w >> 2) == half) {
            int wq = (w & 3) * 16;
#pragma unroll
            for (int kc = 0; kc < 4; kc++) {
                int qrow = wq + (tt & 1) * 8 + lr8;
                int qcol = kc * 16 + (tt >> 1) * 8;
                ldsm4(qa[kc][0], qa[kc][1], qa[kc][2], qa[kc][3],
                      sptr(sK + qrow * SKP + qcol));
#pragma unroll
                for (int j = 0; j < 4; j++)
                    qa[kc][j] = scale8(qa[kc][j]);   // fold 1/sqrt(D)=0.125 (exact)
            }
        }
    }

    float o[8][4];
#pragma unroll
    for (int nt = 0; nt < 8; nt++)
#pragma unroll
        for (int j = 0; j < 4; j++) o[nt][j] = 0.0f;
    float m_r = -1e30f, m_r8 = -1e30f;
    float l_r = 0.0f,   l_r8 = 0.0f;

    const int nkt = 2 * qt + 2;

    // prefetch K/V tile 0
    uint4 pk[2], pv[2];
    {
        size_t base = (size_t)(b * TT) * C3 + h * DD;
#pragma unroll
        for (int i = 0; i < 2; i++) {
            int row = (tid >> 3) + i * 32;
            int c8  = (tid & 7) * 8;
            pk[i] = *(const uint4*)(qkv + base + (size_t)row * C3 + CC + c8);
            pv[i] = *(const uint4*)(qkv + base + (size_t)row * C3 + 2 * CC + c8);
        }
    }

    for (int kt = 0; kt < nkt; kt++) {
        __syncthreads();
#pragma unroll
        for (int i = 0; i < 2; i++) {
            int row = (tid >> 3) + i * 32;
            int c8  = (tid & 7) * 8;
            *(uint4*)(sK + row * SKP + c8) = pk[i];
            *(uint4*)(sV + row * SKP + c8) = pv[i];
        }
        __syncthreads();

        if (kt + 1 < nkt) {
            size_t base = (size_t)(b * TT + (kt + 1) * 64) * C3 + h * DD;
#pragma unroll
            for (int i = 0; i < 2; i++) {
                int row = (tid >> 3) + i * 32;
                int c8  = (tid & 7) * 8;
                pk[i] = *(const uint4*)(qkv + base + (size_t)row * C3 + CC + c8);
                pv[i] = *(const uint4*)(qkv + base + (size_t)row * C3 + 2 * CC + c8);
            }
        }

        if (kt * 64 <= qt * 128 + w * 16 + 15) {
            // ---- scores: S = Q·K^T ----
            float s[8][4];
#pragma unroll
            for (int nt = 0; nt < 8; nt++)
#pragma unroll
                for (int j = 0; j < 4; j++) s[nt][j] = 0.0f;

#pragma unroll
            for (int kc = 0; kc < 4; kc++) {
                unsigned kb[8][2];
#pragma unroll
                for (int i = 0; i < 4; i++) {
                    int nrow = (2 * i + (tt >> 1)) * 8 + lr8;
                    int ncol = kc * 16 + (tt & 1) * 8;
                    ldsm4(kb[2 * i][0], kb[2 * i][1], kb[2 * i + 1][0], kb[2 * i + 1][1],
                          sptr(sK + nrow * SKP + ncol));
                }
#pragma unroll
                for (int nt = 0; nt < 8; nt++)
                    mma16816(s[nt], qa[kc], kb[nt][0], kb[nt][1]);
            }

            // ---- causal mask ----
            if (kt >= 2 * qt) {
                int colb = kt * 64 + cq * 2;
#pragma unroll
                for (int nt = 0; nt < 8; nt++) {
                    int c0 = colb + nt * 8;
                    if (c0 > rowr)      s[nt][0] = -1e30f;
                    if (c0 + 1 > rowr)  s[nt][1] = -1e30f;
                    if (c0 > rowr8)     s[nt][2] = -1e30f;
                    if (c0 + 1 > rowr8) s[nt][3] = -1e30f;
                }
            }

            // ---- online softmax ----
            float mr = -1e30f, mr8 = -1e30f;
#pragma unroll
            for (int nt = 0; nt < 8; nt++) {
                mr  = fmaxf(mr,  fmaxf(s[nt][0], s[nt][1]));
                mr8 = fmaxf(mr8, fmaxf(s[nt][2], s[nt][3]));
            }
            mr  = fmaxf(mr,  __shfl_xor_sync(0xffffffffu, mr, 1));
            mr  = fmaxf(mr,  __shfl_xor_sync(0xffffffffu, mr, 2));
            mr8 = fmaxf(mr8, __shfl_xor_sync(0xffffffffu, mr8, 1));
            mr8 = fmaxf(mr8, __shfl_xor_sync(0xffffffffu, mr8, 2));

            float mn  = fmaxf(m_r, mr);
            float mn8 = fmaxf(m_r8, mr8);
            float ar  = __expf(m_r - mn);
            float ar8 = __expf(m_r8 - mn8);
            m_r = mn; m_r8 = mn8;

            float lsr = 0.f, lsr8 = 0.f;
#pragma unroll
            for (int nt = 0; nt < 8; nt++) {
                float p0 = __expf(s[nt][0] - m_r);
                float p1 = __expf(s[nt][1] - m_r);
                float p2 = __expf(s[nt][2] - m_r8);
                float p3 = __expf(s[nt][3] - m_r8);
                lsr += p0 + p1; lsr8 += p2 + p3;
                s[nt][0] = p0; s[nt][1] = p1; s[nt][2] = p2; s[nt][3] = p3;
                o[nt][0] *= ar; o[nt][1] *= ar; o[nt][2] *= ar8; o[nt][3] *= ar8;
            }
            l_r  = l_r  * ar  + lsr;
            l_r8 = l_r8 * ar8 + lsr8;

            // ---- PV: O += P·V ----
#pragma unroll
            for (int kc = 0; kc < 4; kc++) {
                unsigned pa[4];
                pa[0] = pack2(s[2 * kc][0],     s[2 * kc][1]);
                pa[1] = pack2(s[2 * kc][2],     s[2 * kc][3]);
                pa[2] = pack2(s[2 * kc + 1][0], s[2 * kc + 1][1]);
                pa[3] = pack2(s[2 * kc + 1][2], s[2 * kc + 1][3]);

                unsigned vb[8][2];
#pragma unroll
                for (int i = 0; i < 4; i++) {
                    int vrow = kc * 16 + (tt & 1) * 8 + lr8;
                    int vcol = (2 * i + (tt >> 1)) * 8;
                    ldsm4t(vb[2 * i][0], vb[2 * i][1], vb[2 * i + 1][0], vb[2 * i + 1][1],
                           sptr(sV + vrow * SKP + vcol));
                }
#pragma unroll
                for (int nt = 0; nt < 8; nt++)
                    mma16816(o[nt], pa, vb[nt][0], vb[nt][1]);
            }
        }
    }

    l_r  += __shfl_xor_sync(0xffffffffu, l_r, 1);
    l_r  += __shfl_xor_sync(0xffffffffu, l_r, 2);
    l_r8 += __shfl_xor_sync(0xffffffffu, l_r8, 1);
    l_r8 += __shfl_xor_sync(0xffffffffu, l_r8, 2);
    float inv  = 1.0f / l_r;
    float inv8 = 1.0f / l_r8;

#pragma unroll
    for (int nt = 0; nt < 8; nt++) {
        size_t a0 = (size_t)(b * TT + rowr)  * CC + h * DD + nt * 8 + cq * 2;
        size_t a1 = (size_t)(b * TT + rowr8) * CC + h * DD + nt * 8 + cq * 2;
        *(unsigned*)(outp + a0) = pack2(o[nt][0] * inv,  o[nt][1] * inv);
        *(unsigned*)(outp + a1) = pack2(o[nt][2] * inv8, o[nt][3] * inv8);
    }
}

// ---------------------------------------------------------------------------
extern "C" void kernel_launch(void* const* d_in, const int* in_sizes, int n_in,
                              void* d_out, int out_size)
{
    const float* x     = (const float*)d_in[0];
    const float* w_qkv = (const float*)d_in[1];
    const float* w_out = (const float*)d_in[2];
    const float* b_out = (const float*)d_in[3];
    float* out = (float*)d_out;

    __half *x16, *wq16, *wo16, *qkv16, *at16;
    cudaGetSymbolAddress((void**)&x16,   g_x16);
    cudaGetSymbolAddress((void**)&wq16,  g_wq16);
    cudaGetSymbolAddress((void**)&wo16,  g_wo16);
    cudaGetSymbolAddress((void**)&qkv16, g_qkv16);
    cudaGetSymbolAddress((void**)&at16,  g_at16);

    // 0) round inputs to fp16
    {
        int n1 = MTOT * CC;
        round_f16<<<(n1 / 4 + 255) / 256, 256>>>(x, x16, n1);
        int n2 = C3 * CC;
        round_f16<<<(n2 / 4 + 255) / 256, 256>>>(w_qkv, wq16, n2);
        int n3 = CC * CC;
        round_f16<<<(n3 / 4 + 255) / 256, 256>>>(w_out, wo16, n3);
    }

    // 1) QKV projection -> fp16
    {
        dim3 grid(C3 / 128, MTOT / 128);
        gemm_f16<<<grid, 256>>>(x16, wq16, nullptr, qkv16, nullptr, MTOT, C3, CC);
    }

    // 2) causal flash attention -> fp16
    {
        dim3 grid(TT / 128, BB * HH);
        flash_attn_f16<<<grid, 256>>>(qkv16, at16);
    }

    // 3) out projection + bias -> fp32 output
    {
        dim3 grid(CC / 128, MTOT / 128);
        gemm_f16<<<grid, 256>>>(at16, wo16, out, nullptr, b_out, MTOT, CC, CC);
    }
}